// round 2
// baseline (speedup 1.0000x reference)
#include <cuda_runtime.h>
#include <math.h>

#define BB 16
#define SS 1024
#define DD 128
#define HH 4
#define NEGM (-1e9f)

// ---------------- scratch (device globals: allocation-free) ----------------
__device__ __align__(16) float g_stats[BB * 2];                 // mu, rstd per batch
__device__ __align__(16) float g_Q[BB * HH * SS * DD];          // 32 MB
__device__ __align__(16) float g_K[BB * HH * SS * DD];          // 32 MB
__device__ __align__(16) float g_V[BB * HH * SS * DD];          // 32 MB
__device__ __align__(16) float g_ctx[BB * HH * SS * DD];        // 32 MB
__device__ unsigned g_mask[HH * SS * (SS / 32)];                // 512 KB bitmaps
__device__ int g_i64;

// ---------------- kernel 0: edge dtype detect (int64 vs int32) -------------
__global__ void detect_kernel(const int* edge_raw) {
    if (threadIdx.x == 0) {
        int all0 = 1;
        for (int j = 1; j < 256; j += 2) all0 &= (edge_raw[j] == 0);
        g_i64 = all0;   // int64 little-endian with values 0..4 -> all high words 0
    }
}

// ---------------- kernel 1: layernorm stats over (S,D) per batch -----------
__global__ void stats_kernel(const float* __restrict__ x) {
    int b = blockIdx.x;
    int tid = threadIdx.x;            // 256 threads
    const float4* xp = (const float4*)(x + (size_t)b * SS * DD);
    float s = 0.f, sq = 0.f;
    const int n4 = SS * DD / 4;       // 32768
    for (int j = tid; j < n4; j += 256) {
        float4 v = xp[j];
        s  += v.x + v.y + v.z + v.w;
        sq += v.x * v.x + v.y * v.y + v.z * v.z + v.w * v.w;
    }
    __shared__ float sh[512];
    sh[tid] = s; sh[256 + tid] = sq;
    __syncthreads();
    for (int off = 128; off > 0; off >>= 1) {
        if (tid < off) { sh[tid] += sh[tid + off]; sh[256 + tid] += sh[256 + tid + off]; }
        __syncthreads();
    }
    if (tid == 0) {
        const float inv_n = 1.f / (float)(SS * DD);
        float mu = sh[0] * inv_n;
        float var = sh[256] * inv_n - mu * mu;
        g_stats[b * 2 + 0] = mu;
        g_stats[b * 2 + 1] = rsqrtf(var + 1e-5f);
    }
}

// ---------------- kernel 2: mask bitmaps -----------------------------------
__global__ void mask_kernel(const int* __restrict__ edge_raw) {
    int s = blockIdx.x;               // 1024
    int w = threadIdx.x;              // 32 threads -> one 32-bit word each
    int i64 = g_i64;
    unsigned mm[HH] = {0u, 0u, 0u, 0u};
    for (int j = 0; j < 32; j++) {
        int idx = s * SS + w * 32 + j;
        int e = i64 ? edge_raw[2 * idx] : edge_raw[idx];
        if (e >= 1 && e <= HH) mm[e - 1] |= (1u << j);
    }
#pragma unroll
    for (int h = 0; h < HH; h++) g_mask[((size_t)h * SS + s) * 32 + w] = mm[h];
}

// ---------------- kernel 3: fused layernorm + QKV projection ---------------
// GEMM: [16384 x 128] x [1536 x 128]^T  -> scatter into g_Q/g_K/g_V (+bias)
__global__ void __launch_bounds__(256) qkv_kernel(const float* __restrict__ x,
                                                  const float* __restrict__ W_in,
                                                  const float* __restrict__ b_in) {
    __shared__ float As[64][132];
    __shared__ float Bs[64][132];
    int n0 = blockIdx.x * 64;         // 0..1535 (col of flattened [H*3D])
    int m0 = blockIdx.y * 64;         // 0..16383 (row of B*S)
    int b = m0 >> 10;
    float mu = g_stats[b * 2], rstd = g_stats[b * 2 + 1];
    int tid = threadIdx.x;

    // load+normalize A tile (64x128) and load W tile (64x128)
#pragma unroll
    for (int j = 0; j < 8; j++) {
        int idx = j * 256 + tid;
        int r = idx >> 5, c4 = idx & 31;
        float4 v = ((const float4*)x)[(size_t)(m0 + r) * 32 + c4];
        v.x = (v.x - mu) * rstd; v.y = (v.y - mu) * rstd;
        v.z = (v.z - mu) * rstd; v.w = (v.w - mu) * rstd;
        *(float4*)&As[r][c4 * 4] = v;
    }
#pragma unroll
    for (int j = 0; j < 8; j++) {
        int idx = j * 256 + tid;
        int r = idx >> 5, c4 = idx & 31;
        *(float4*)&Bs[r][c4 * 4] = ((const float4*)W_in)[(size_t)(n0 + r) * 32 + c4];
    }
    __syncthreads();

    int tx = tid & 15, ty = tid >> 4;   // ty 0..15 rows-group, tx 0..15 cols-group
    float acc[4][4];
#pragma unroll
    for (int a = 0; a < 4; a++)
#pragma unroll
        for (int c = 0; c < 4; c++) acc[a][c] = 0.f;

#pragma unroll 4
    for (int k4 = 0; k4 < 32; k4++) {
        float4 av[4], wv[4];
#pragma unroll
        for (int sr = 0; sr < 4; sr++) av[sr] = *(float4*)&As[ty + 16 * sr][k4 * 4];
#pragma unroll
        for (int sc = 0; sc < 4; sc++) wv[sc] = *(float4*)&Bs[tx + 16 * sc][k4 * 4];
#pragma unroll
        for (int sr = 0; sr < 4; sr++)
#pragma unroll
            for (int sc = 0; sc < 4; sc++) {
                acc[sr][sc] = fmaf(av[sr].x, wv[sc].x, acc[sr][sc]);
                acc[sr][sc] = fmaf(av[sr].y, wv[sc].y, acc[sr][sc]);
                acc[sr][sc] = fmaf(av[sr].z, wv[sc].z, acc[sr][sc]);
                acc[sr][sc] = fmaf(av[sr].w, wv[sc].w, acc[sr][sc]);
            }
    }

    // scatter: n -> (h, e); e<128 Q, e<256 K, else V (tile is homogeneous)
    int h = n0 / 384;
    int e0 = n0 % 384;
    float* dst = (e0 < 128) ? g_Q : (e0 < 256 ? g_K : g_V);
    int dbase = e0 & 127;
#pragma unroll
    for (int sr = 0; sr < 4; sr++) {
        int m = m0 + ty + 16 * sr;
        int s = m & 1023;
#pragma unroll
        for (int sc = 0; sc < 4; sc++) {
            int nc = tx + 16 * sc;            // 0..63 within tile
            int n = n0 + nc;
            float val = acc[sr][sc] + b_in[n];
            dst[((size_t)(b * HH + h) * SS + s) * DD + (dbase + nc)] = val;
        }
    }
}

// ---------------- kernel 4: flash attention (fp32) -------------------------
// block: 64 q-rows, 256 threads: thread = (row r, d-slice i of 32)
__global__ void __launch_bounds__(256) attn_kernel() {
    extern __shared__ float sm[];
    float4* ks4 = (float4*)sm;                 // 64 x 128 floats
    float4* vs4 = (float4*)(sm + 64 * DD);     // 64 x 128 floats

    int mt = blockIdx.x, h = blockIdx.y, b = blockIdx.z;
    int tid = threadIdx.x;
    int r = tid >> 2, i = tid & 3;
    int m = mt * 64 + r;

    const float* qbase = g_Q + ((size_t)(b * HH + h) * SS + m) * DD + i * 32;
    float4 qv[8];
#pragma unroll
    for (int j = 0; j < 8; j++) {
        int dd = (j + 2 * i) & 7;              // pre-rotated to match staggered K/V slots
        qv[j] = *(const float4*)(qbase + dd * 4);
    }
    float4 accv[8];
#pragma unroll
    for (int j = 0; j < 8; j++) accv[j] = make_float4(0.f, 0.f, 0.f, 0.f);
    float mrow = -INFINITY, lsum = 0.f;

    const float4* kg0 = (const float4*)(g_K + ((size_t)(b * HH + h) * SS) * DD);
    const float4* vg0 = (const float4*)(g_V + ((size_t)(b * HH + h) * SS) * DD);
    const unsigned* mwp = g_mask + ((size_t)h * SS + m) * 32;
    const float SCALE = 0.08838834764831845f;  // 1/sqrt(128)

    for (int kt = 0; kt < 16; kt++) {
        __syncthreads();
        const float4* kg = kg0 + (size_t)kt * 64 * 32;
        const float4* vg = vg0 + (size_t)kt * 64 * 32;
#pragma unroll
        for (int j = 0; j < 8; j++) {
            ks4[j * 256 + tid] = kg[j * 256 + tid];
            vs4[j * 256 + tid] = vg[j * 256 + tid];
        }
        __syncthreads();

        unsigned mw0 = mwp[kt * 2], mw1 = mwp[kt * 2 + 1];

#pragma unroll 1
        for (int cc = 0; cc < 8; cc++) {       // 8 columns per chunk
            float p[8];
#pragma unroll
            for (int c = 0; c < 8; c++) p[c] = 0.f;

            // partial scores over this thread's 32 d's (bank-staggered slots)
#pragma unroll
            for (int d4 = 0; d4 < 8; d4++) {
                int slot = i * 8 + ((d4 + 2 * i) & 7);
#pragma unroll
                for (int c = 0; c < 8; c++) {
                    float4 k4 = ks4[(cc * 8 + c) * 32 + slot];
                    p[c] = fmaf(qv[d4].x, k4.x, p[c]);
                    p[c] = fmaf(qv[d4].y, k4.y, p[c]);
                    p[c] = fmaf(qv[d4].z, k4.z, p[c]);
                    p[c] = fmaf(qv[d4].w, k4.w, p[c]);
                }
            }
            // butterfly across the 4 d-slice lanes -> full dot products
#pragma unroll
            for (int c = 0; c < 8; c++) {
                p[c] += __shfl_xor_sync(0xffffffffu, p[c], 1);
                p[c] += __shfl_xor_sync(0xffffffffu, p[c], 2);
            }
            // scale + additive mask, chunk max
            unsigned mw = (cc < 4) ? mw0 : mw1;
            int bit0 = (cc & 3) * 8;
            float cmax = -INFINITY;
#pragma unroll
            for (int c = 0; c < 8; c++) {
                float madd = ((mw >> (bit0 + c)) & 1u) ? 0.f : NEGM;
                p[c] = fmaf(p[c], SCALE, madd);
                cmax = fmaxf(cmax, p[c]);
            }
            // online softmax update
            float mnew = fmaxf(mrow, cmax);
            if (mnew > mrow) {
                float corr = __expf(mrow - mnew);
                lsum *= corr;
#pragma unroll
                for (int j = 0; j < 8; j++) {
                    accv[j].x *= corr; accv[j].y *= corr;
                    accv[j].z *= corr; accv[j].w *= corr;
                }
                mrow = mnew;
            }
#pragma unroll
            for (int c = 0; c < 8; c++) {
                p[c] = __expf(p[c] - mrow);
                lsum += p[c];
            }
            // accumulate P*V on this thread's d-slice
#pragma unroll
            for (int d4 = 0; d4 < 8; d4++) {
                int slot = i * 8 + ((d4 + 2 * i) & 7);
#pragma unroll
                for (int c = 0; c < 8; c++) {
                    float4 v4 = vs4[(cc * 8 + c) * 32 + slot];
                    accv[d4].x = fmaf(p[c], v4.x, accv[d4].x);
                    accv[d4].y = fmaf(p[c], v4.y, accv[d4].y);
                    accv[d4].z = fmaf(p[c], v4.z, accv[d4].z);
                    accv[d4].w = fmaf(p[c], v4.w, accv[d4].w);
                }
            }
        }
    }
    float rl = 1.f / lsum;
    float* obase = g_ctx + ((size_t)(b * HH + h) * SS + m) * DD + i * 32;
#pragma unroll
    for (int j = 0; j < 8; j++) {
        int dd = (j + 2 * i) & 7;
        float4 o;
        o.x = accv[j].x * rl; o.y = accv[j].y * rl;
        o.z = accv[j].z * rl; o.w = accv[j].w * rl;
        *(float4*)(obase + dd * 4) = o;
    }
}

// ---------------- kernel 5: output projection + concat ---------------------
// per (m-tile, h): [64 x 128] x [128 x 128]^T + bias -> out[b,s,h*128+e]
__global__ void __launch_bounds__(256) outproj_kernel(const float* __restrict__ W_out,
                                                      const float* __restrict__ b_out,
                                                      float* __restrict__ out) {
    extern __shared__ float sm[];
    float (*Cs)[132] = (float(*)[132])sm;               // 64 rows ctx
    float (*Ws)[132] = (float(*)[132])(sm + 64 * 132);  // 128 rows W_out[h]
    int m0 = blockIdx.x * 64;
    int h = blockIdx.y;
    int b = m0 >> 10;
    int tid = threadIdx.x;

    const float4* cg = (const float4*)(g_ctx + ((size_t)(b * HH + h) * SS + (m0 & 1023)) * DD);
#pragma unroll
    for (int j = 0; j < 8; j++) {
        int idx = j * 256 + tid;
        int rr = idx >> 5, c4 = idx & 31;
        *(float4*)&Cs[rr][c4 * 4] = cg[rr * 32 + c4];
    }
    const float4* wg = (const float4*)(W_out + (size_t)h * DD * DD);
#pragma unroll
    for (int j = 0; j < 16; j++) {
        int idx = j * 256 + tid;
        int rr = idx >> 5, c4 = idx & 31;
        *(float4*)&Ws[rr][c4 * 4] = wg[idx];
    }
    __syncthreads();

    int tx = tid & 15, ty = tid >> 4;
    float acc[4][8];
#pragma unroll
    for (int a = 0; a < 4; a++)
#pragma unroll
        for (int c = 0; c < 8; c++) acc[a][c] = 0.f;

#pragma unroll 2
    for (int k4 = 0; k4 < 32; k4++) {
        float4 av[4], wv[8];
#pragma unroll
        for (int sr = 0; sr < 4; sr++) av[sr] = *(float4*)&Cs[ty + 16 * sr][k4 * 4];
#pragma unroll
        for (int sc = 0; sc < 8; sc++) wv[sc] = *(float4*)&Ws[tx + 16 * sc][k4 * 4];
#pragma unroll
        for (int sr = 0; sr < 4; sr++)
#pragma unroll
            for (int sc = 0; sc < 8; sc++) {
                acc[sr][sc] = fmaf(av[sr].x, wv[sc].x, acc[sr][sc]);
                acc[sr][sc] = fmaf(av[sr].y, wv[sc].y, acc[sr][sc]);
                acc[sr][sc] = fmaf(av[sr].z, wv[sc].z, acc[sr][sc]);
                acc[sr][sc] = fmaf(av[sr].w, wv[sc].w, acc[sr][sc]);
            }
    }

#pragma unroll
    for (int sr = 0; sr < 4; sr++) {
        int m = m0 + ty + 16 * sr;
#pragma unroll
        for (int sc = 0; sc < 8; sc++) {
            int e = tx + 16 * sc;
            out[(size_t)m * (HH * DD) + h * DD + e] = acc[sr][sc] + b_out[h * DD + e];
        }
    }
}

// ---------------- launch ----------------------------------------------------
extern "C" void kernel_launch(void* const* d_in, const int* in_sizes, int n_in,
                              void* d_out, int out_size) {
    const float* x     = (const float*)d_in[0];
    const int*   edge  = (const int*)d_in[1];   // int32 view; detect kernel handles int64
    const float* W_in  = (const float*)d_in[2];
    const float* b_in  = (const float*)d_in[3];
    const float* W_out = (const float*)d_in[4];
    const float* b_out = (const float*)d_in[5];
    float* out = (float*)d_out;

    cudaFuncSetAttribute(attn_kernel, cudaFuncAttributeMaxDynamicSharedMemorySize, 64 * DD * 2 * 4);
    cudaFuncSetAttribute(outproj_kernel, cudaFuncAttributeMaxDynamicSharedMemorySize, (64 + 128) * 132 * 4);

    detect_kernel<<<1, 32>>>(edge);
    stats_kernel<<<BB, 256>>>(x);
    mask_kernel<<<SS, 32>>>(edge);
    qkv_kernel<<<dim3(24, 256), 256>>>(x, W_in, b_in);
    attn_kernel<<<dim3(16, HH, BB), 256, 64 * DD * 2 * 4>>>();
    outproj_kernel<<<dim3(256, HH), 256, (64 + 128) * 132 * 4>>>(W_out, b_out, out);
}